// round 3
// baseline (speedup 1.0000x reference)
#include <cuda_runtime.h>
#include <math.h>

// ---------------- problem constants ----------------
#define MAXN 20000
#define MAXE 320000
#define MAXET (MAXN + MAXE)
#define NGR 32

// ---------------- device scratch (no allocs allowed) ----------------
__device__ float g_h768[MAXN * 768];
__device__ float g_T[(size_t)MAXN * 1024];
__device__ float g_G[(size_t)MAXN * 1024];
__device__ float g_x1[(size_t)MAXN * 1024];
__device__ float g_x2[(size_t)MAXN * 1024];
__device__ float g_x3[MAXN * 256];
__device__ float g_es[MAXN * 4];
__device__ float g_ed[MAXN * 4];
__device__ int   g_deg[MAXN];
__device__ int   g_off[MAXN + 1];
__device__ int   g_cur[MAXN];
__device__ int   g_csr[MAXET];
__device__ float g_psum[NGR * 256];
__device__ float g_pmax[NGR * 256];
__device__ int   g_pcnt[NGR];

// Device-side buffer table: lets kernel_launch stay pure kernel launches
// (no cudaGetSymbolAddress / host APIs inside graph capture).
#define BUF_H768 0
#define BUF_T    1
#define BUF_G    2
#define BUF_X1   3
#define BUF_X2   4
#define BUF_X3   5
__device__ float* const g_fptr[6] = { g_h768, g_T, g_G, g_x1, g_x2, g_x3 };

// ---------------- helpers ----------------
__device__ __forceinline__ float atomicMaxF(float* addr, float value) {
    if (value >= 0.f)
        return __int_as_float(atomicMax((int*)addr, __float_as_int(value)));
    else
        return __uint_as_float(atomicMin((unsigned int*)addr, __float_as_uint(value)));
}

// ---------------- CSR build ----------------
__global__ void k_zero_deg(int n) {
    int i = blockIdx.x * 256 + threadIdx.x;
    if (i < n) g_deg[i] = 0;
}

__global__ void k_count_deg(const int* __restrict__ ei, int E, int N) {
    int i = blockIdx.x * 256 + threadIdx.x;
    if (i >= E + N) return;
    int dst = (i < E) ? ei[E + i] : (i - E);
    atomicAdd(&g_deg[dst], 1);
}

__global__ void __launch_bounds__(1024) k_scan_deg(int n) {
    const int NT = 1024;
    int tid = threadIdx.x;
    int chunk = (n + NT - 1) / NT;
    int b0 = tid * chunk;
    int lsum = 0;
    for (int i = 0; i < chunk; i++) {
        int j = b0 + i;
        if (j < n) lsum += g_deg[j];
    }
    __shared__ int s[NT];
    s[tid] = lsum;
    __syncthreads();
    for (int o = 1; o < NT; o <<= 1) {
        int t = (tid >= o) ? s[tid - o] : 0;
        __syncthreads();
        s[tid] += t;
        __syncthreads();
    }
    int run = s[tid] - lsum;  // exclusive prefix
    for (int i = 0; i < chunk; i++) {
        int j = b0 + i;
        if (j < n) { g_off[j] = run; g_cur[j] = run; run += g_deg[j]; }
    }
    if (tid == NT - 1) g_off[n] = s[NT - 1];
}

__global__ void k_scatter_edges(const int* __restrict__ ei, int E, int N) {
    int i = blockIdx.x * 256 + threadIdx.x;
    if (i >= E + N) return;
    int src, dst;
    if (i < E) { src = ei[i]; dst = ei[E + i]; }
    else       { src = i - E; dst = i - E; }
    int pos = atomicAdd(&g_cur[dst], 1);
    g_csr[pos] = src;
}

// ---------------- SGEMM: C = act(A @ W + bias) ----------------
// A:[M,K] row-major (scratch id or external), W:[K,N] row-major. ACT: 0 none, 1 elu
#define BM 64
#define BN 64
#define BKK 16
template <int ACT>
__global__ void __launch_bounds__(256) k_sgemm(const float* __restrict__ Aext, int a_id,
                                               const float* __restrict__ W,
                                               const float* __restrict__ bias, int c_id,
                                               int M, int N, int K) {
    const float* __restrict__ A = Aext ? Aext : g_fptr[a_id];
    float* __restrict__ C = g_fptr[c_id];
    __shared__ float As[BKK][BM + 1];
    __shared__ float Ws[BKK][BN + 1];
    int tid = threadIdx.x;
    int row0 = blockIdx.y * BM, col0 = blockIdx.x * BN;
    int tx = tid & 15, ty = tid >> 4;
    float acc[4][4] = {};
    int arow = tid >> 2;        // 0..63
    int akg = (tid & 3) * 4;    // 0,4,8,12
    int wrow = tid >> 4;        // 0..15
    int wcol = (tid & 15) * 4;  // 0..60

    for (int k0 = 0; k0 < K; k0 += BKK) {
        float4 av = make_float4(0.f, 0.f, 0.f, 0.f);
        int gr = row0 + arow;
        if (gr < M) av = *(const float4*)(A + (size_t)gr * K + k0 + akg);
        As[akg + 0][arow] = av.x;
        As[akg + 1][arow] = av.y;
        As[akg + 2][arow] = av.z;
        As[akg + 3][arow] = av.w;

        float4 wv = *(const float4*)(W + (size_t)(k0 + wrow) * N + col0 + wcol);
        Ws[wrow][wcol + 0] = wv.x;
        Ws[wrow][wcol + 1] = wv.y;
        Ws[wrow][wcol + 2] = wv.z;
        Ws[wrow][wcol + 3] = wv.w;
        __syncthreads();

#pragma unroll
        for (int k = 0; k < BKK; k++) {
            float a[4], b[4];
#pragma unroll
            for (int i = 0; i < 4; i++) a[i] = As[k][ty * 4 + i];
#pragma unroll
            for (int j = 0; j < 4; j++) b[j] = Ws[k][tx * 4 + j];
#pragma unroll
            for (int i = 0; i < 4; i++)
#pragma unroll
                for (int j = 0; j < 4; j++) acc[i][j] += a[i] * b[j];
        }
        __syncthreads();
    }

#pragma unroll
    for (int i = 0; i < 4; i++) {
        int r = row0 + ty * 4 + i;
        if (r >= M) continue;
        int c = col0 + tx * 4;
        float4 v;
        v.x = acc[i][0]; v.y = acc[i][1]; v.z = acc[i][2]; v.w = acc[i][3];
        if (bias) {
            v.x += bias[c + 0]; v.y += bias[c + 1];
            v.z += bias[c + 2]; v.w += bias[c + 3];
        }
        if (ACT == 1) {
            v.x = v.x > 0.f ? v.x : (expf(v.x) - 1.0f);
            v.y = v.y > 0.f ? v.y : (expf(v.y) - 1.0f);
            v.z = v.z > 0.f ? v.z : (expf(v.z) - 1.0f);
            v.w = v.w > 0.f ? v.w : (expf(v.w) - 1.0f);
        }
        *(float4*)(C + (size_t)r * N + c) = v;
    }
}

// ---------------- attention dot products ----------------
// es[n,h] = sum_c T[n, h*C+c] * asrc[h,c];  ed likewise.
__global__ void k_att_dots(const float* __restrict__ as_, const float* __restrict__ ad_,
                           int NH, int H, int C) {
    const float* __restrict__ T = g_T;
    int gw = (blockIdx.x * blockDim.x + threadIdx.x) >> 5;
    int lane = threadIdx.x & 31;
    if (gw >= NH) return;
    int n = gw / H, h = gw - n * H;
    const float* row = T + (size_t)n * H * C + (size_t)h * C;
    float a = 0.f, d = 0.f;
    for (int c = lane; c < C; c += 32) {
        float v = row[c];
        a += v * as_[h * C + c];
        d += v * ad_[h * C + c];
    }
    for (int o = 16; o; o >>= 1) {
        a += __shfl_xor_sync(0xffffffffu, a, o);
        d += __shfl_xor_sync(0xffffffffu, d, o);
    }
    if (lane == 0) { g_es[gw] = a; g_ed[gw] = d; }
}

// ---------------- GAT aggregation (per-dst-node softmax + weighted gather) ----------------
template <int H, int CPT>
__global__ void __launch_bounds__(256) k_gat_agg(const float* __restrict__ bias) {
    const int F = 256 * CPT;  // = H*256
    const float* __restrict__ T = g_T;
    const float* __restrict__ es = g_es;
    float* __restrict__ out = g_G;
    int node = blockIdx.x;
    int tid = threadIdx.x;
    int lane = tid & 31, wid = tid >> 5;
    int beg = g_off[node], end = g_off[node + 1];

    float edv[H];
#pragma unroll
    for (int h = 0; h < H; h++) edv[h] = g_ed[node * H + h];

    __shared__ float s_red[8][H];
    __shared__ float s_hmax[H];
    __shared__ float s_hden[H];

    // pass 1: per-head max logit
    float lmax[H];
#pragma unroll
    for (int h = 0; h < H; h++) lmax[h] = -INFINITY;
    for (int e = beg + tid; e < end; e += 256) {
        int s = g_csr[e];
#pragma unroll
        for (int h = 0; h < H; h++) {
            float l = es[s * H + h] + edv[h];
            l = l > 0.f ? l : 0.2f * l;
            lmax[h] = fmaxf(lmax[h], l);
        }
    }
#pragma unroll
    for (int h = 0; h < H; h++)
        for (int o = 16; o; o >>= 1) lmax[h] = fmaxf(lmax[h], __shfl_xor_sync(0xffffffffu, lmax[h], o));
    if (lane == 0) {
#pragma unroll
        for (int h = 0; h < H; h++) s_red[wid][h] = lmax[h];
    }
    __syncthreads();
    if (tid == 0) {
#pragma unroll
        for (int h = 0; h < H; h++) {
            float m = s_red[0][h];
            for (int w = 1; w < 8; w++) m = fmaxf(m, s_red[w][h]);
            s_hmax[h] = m;
        }
    }
    __syncthreads();

    // pass 2: denominator
    float lden[H] = {};
    for (int e = beg + tid; e < end; e += 256) {
        int s = g_csr[e];
#pragma unroll
        for (int h = 0; h < H; h++) {
            float l = es[s * H + h] + edv[h];
            l = l > 0.f ? l : 0.2f * l;
            lden[h] += expf(l - s_hmax[h]);
        }
    }
#pragma unroll
    for (int h = 0; h < H; h++)
        for (int o = 16; o; o >>= 1) lden[h] += __shfl_xor_sync(0xffffffffu, lden[h], o);
    if (lane == 0) {
#pragma unroll
        for (int h = 0; h < H; h++) s_red[wid][h] = lden[h];
    }
    __syncthreads();
    if (tid == 0) {
#pragma unroll
        for (int h = 0; h < H; h++) {
            float m = 0.f;
            for (int w = 0; w < 8; w++) m += s_red[w][h];
            s_hden[h] = m;
        }
    }
    __syncthreads();

    // pass 3: weighted gather
    float acc[CPT] = {};
    __shared__ int s_src[256];
    __shared__ float s_alpha[256 * H];
    for (int cb = beg; cb < end; cb += 256) {
        int cn = min(256, end - cb);
        if (tid < cn) {
            int s = g_csr[cb + tid];
            s_src[tid] = s;
#pragma unroll
            for (int h = 0; h < H; h++) {
                float l = es[s * H + h] + edv[h];
                l = l > 0.f ? l : 0.2f * l;
                s_alpha[tid * H + h] = expf(l - s_hmax[h]) / (s_hden[h] + 1e-16f);
            }
        }
        __syncthreads();
        if (CPT == 4) {
            const int head = tid >> 6;
            for (int j = 0; j < cn; j++) {
                int s = s_src[j];
                float alpha = s_alpha[j * H + head];
                float4 v = *(const float4*)(T + (size_t)s * F + tid * 4);
                acc[0] += alpha * v.x;
                acc[1] += alpha * v.y;
                acc[2] += alpha * v.z;
                acc[3] += alpha * v.w;
            }
        } else {
            for (int j = 0; j < cn; j++) {
                int s = s_src[j];
                float alpha = s_alpha[j * H];
                acc[0] += alpha * T[(size_t)s * F + tid];
            }
        }
        __syncthreads();
    }
#pragma unroll
    for (int q = 0; q < CPT; q++) {
        int c = tid * CPT + q;
        out[(size_t)node * F + c] = acc[q] + bias[c];
    }
}

// ---------------- LayerNorm + ELU (+ optional residual added AFTER elu) ----------------
// in = g_G always; res/out selected by id (res_id < 0 -> none)
__global__ void __launch_bounds__(256) k_ln_elu(const float* __restrict__ g,
                                                const float* __restrict__ b,
                                                int res_id, int out_id, int F) {
    const float* __restrict__ in = g_G;
    const float* __restrict__ res = (res_id >= 0) ? g_fptr[res_id] : nullptr;
    float* __restrict__ out = g_fptr[out_id];
    int node = blockIdx.x, tid = threadIdx.x;
    const float* row = in + (size_t)node * F;
    float s = 0.f, s2 = 0.f;
    for (int c = tid; c < F; c += 256) {
        float v = row[c];
        s += v;
        s2 += v * v;
    }
    __shared__ float sh[8], sh2[8];
    for (int o = 16; o; o >>= 1) {
        s += __shfl_xor_sync(0xffffffffu, s, o);
        s2 += __shfl_xor_sync(0xffffffffu, s2, o);
    }
    if ((tid & 31) == 0) { sh[tid >> 5] = s; sh2[tid >> 5] = s2; }
    __syncthreads();
    __shared__ float smean, sinv;
    if (tid == 0) {
        float ts = 0.f, t2 = 0.f;
        for (int w = 0; w < 8; w++) { ts += sh[w]; t2 += sh2[w]; }
        float mean = ts / F;
        float var = t2 / F - mean * mean;
        if (var < 0.f) var = 0.f;
        smean = mean;
        sinv = rsqrtf(var + 1e-5f);
    }
    __syncthreads();
    float mean = smean, inv = sinv;
    for (int c = tid; c < F; c += 256) {
        float v = (row[c] - mean) * inv * g[c] + b[c];
        v = v > 0.f ? v : (expf(v) - 1.0f);
        if (res) v += res[(size_t)node * F + c];
        out[(size_t)node * F + c] = v;
    }
}

// ---------------- pooling ----------------
__global__ void k_pool_init() {
    int i = blockIdx.x * 256 + threadIdx.x;
    if (i < NGR * 256) { g_psum[i] = 0.f; g_pmax[i] = -INFINITY; }
    if (i < NGR) g_pcnt[i] = 0;
}

__global__ void k_pool_scatter(const int* __restrict__ batch, int N) {
    int i = blockIdx.x * 256 + threadIdx.x;
    if (i >= N * 256) return;
    int n = i >> 8, c = i & 255;
    int gph = batch[n];
    float v = g_x3[(size_t)n * 256 + c];
    atomicAdd(&g_psum[gph * 256 + c], v);
    atomicMaxF(&g_pmax[gph * 256 + c], v);
    if (c == 0) atomicAdd(&g_pcnt[gph], 1);
}

// ---------------- classifier head ----------------
__global__ void __launch_bounds__(128) k_classify(const float* __restrict__ w1, const float* __restrict__ b1,
                                                  const float* __restrict__ w2, const float* __restrict__ b2,
                                                  float* __restrict__ out) {
    int gph = blockIdx.x, tid = threadIdx.x;
    __shared__ float p[768];
    float cnt = (float)max(g_pcnt[gph], 1);
    for (int j = tid; j < 256; j += 128) {
        float sm = g_psum[gph * 256 + j];
        p[j] = sm / cnt;
        p[256 + j] = g_pmax[gph * 256 + j];
        p[512 + j] = sm;
    }
    __syncthreads();
    float h = b1[tid];
    for (int j = 0; j < 768; j++) h += p[j] * w1[j * 128 + tid];
    h = h > 0.f ? h : 0.f;
    float part = h * w2[tid];
    for (int o = 16; o; o >>= 1) part += __shfl_xor_sync(0xffffffffu, part, o);
    __shared__ float sr[4];
    if ((tid & 31) == 0) sr[tid >> 5] = part;
    __syncthreads();
    if (tid == 0) out[gph] = sr[0] + sr[1] + sr[2] + sr[3] + b2[0];
}

// ---------------- launch (pure kernel launches; graph-capture safe) ----------------
extern "C" void kernel_launch(void* const* d_in, const int* in_sizes, int n_in,
                              void* d_out, int out_size) {
    const float* x = (const float*)d_in[0];
    const int* ei = (const int*)d_in[1];
    const int* batch = (const int*)d_in[2];
    const float* proj_w = (const float*)d_in[3];
    const float* proj_b = (const float*)d_in[4];
    const float* gat1_w = (const float*)d_in[5];
    const float* att1_src = (const float*)d_in[6];
    const float* att1_dst = (const float*)d_in[7];
    const float* gat1_b = (const float*)d_in[8];
    const float* ln1_g = (const float*)d_in[9];
    const float* ln1_b = (const float*)d_in[10];
    const float* gat2_w = (const float*)d_in[11];
    const float* att2_src = (const float*)d_in[12];
    const float* att2_dst = (const float*)d_in[13];
    const float* gat2_b = (const float*)d_in[14];
    const float* ln2_g = (const float*)d_in[15];
    const float* ln2_b = (const float*)d_in[16];
    const float* gat3_w = (const float*)d_in[17];
    const float* att3_src = (const float*)d_in[18];
    const float* att3_dst = (const float*)d_in[19];
    const float* gat3_b = (const float*)d_in[20];
    const float* ln3_g = (const float*)d_in[21];
    const float* ln3_b = (const float*)d_in[22];
    const float* cls1_w = (const float*)d_in[23];
    const float* cls1_b = (const float*)d_in[24];
    const float* cls2_w = (const float*)d_in[25];
    const float* cls2_b = (const float*)d_in[26];
    float* out = (float*)d_out;

    int N = in_sizes[0] / 768;
    int E = in_sizes[1] / 2;
    int ET = E + N;

    // ---- CSR build (dst-grouped incoming edges incl. self-loops) ----
    k_zero_deg<<<(N + 255) / 256, 256>>>(N);
    k_count_deg<<<(ET + 255) / 256, 256>>>(ei, E, N);
    k_scan_deg<<<1, 1024>>>(N);
    k_scatter_edges<<<(ET + 255) / 256, 256>>>(ei, E, N);

    dim3 thr(256);
    int mgrid = (N + BM - 1) / BM;

    // ---- h = elu(x @ proj_w + proj_b) ----
    k_sgemm<1><<<dim3(768 / BN, mgrid), thr>>>(x, 0, proj_w, proj_b, BUF_H768, N, 768, 768);

    // ---- GAT layer 1: 768 -> 4x256 concat ----
    k_sgemm<0><<<dim3(1024 / BN, mgrid), thr>>>(nullptr, BUF_H768, gat1_w, nullptr, BUF_T, N, 1024, 768);
    k_att_dots<<<(N * 4 * 32 + 255) / 256, 256>>>(att1_src, att1_dst, N * 4, 4, 256);
    k_gat_agg<4, 4><<<N, 256>>>(gat1_b);
    k_ln_elu<<<N, 256>>>(ln1_g, ln1_b, -1, BUF_X1, 1024);

    // ---- GAT layer 2: 1024 -> 4x256 concat, residual ----
    k_sgemm<0><<<dim3(1024 / BN, mgrid), thr>>>(nullptr, BUF_X1, gat2_w, nullptr, BUF_T, N, 1024, 1024);
    k_att_dots<<<(N * 4 * 32 + 255) / 256, 256>>>(att2_src, att2_dst, N * 4, 4, 256);
    k_gat_agg<4, 4><<<N, 256>>>(gat2_b);
    k_ln_elu<<<N, 256>>>(ln2_g, ln2_b, BUF_X1, BUF_X2, 1024);

    // ---- GAT layer 3: 1024 -> 1x256 (mean over 1 head = identity) ----
    k_sgemm<0><<<dim3(256 / BN, mgrid), thr>>>(nullptr, BUF_X2, gat3_w, nullptr, BUF_T, N, 256, 1024);
    k_att_dots<<<(N * 1 * 32 + 255) / 256, 256>>>(att3_src, att3_dst, N * 1, 1, 256);
    k_gat_agg<1, 1><<<N, 256>>>(gat3_b);
    k_ln_elu<<<N, 256>>>(ln3_g, ln3_b, -1, BUF_X3, 256);

    // ---- pooling + classifier ----
    k_pool_init<<<(NGR * 256 + 255) / 256, 256>>>();
    k_pool_scatter<<<(N * 256 + 255) / 256, 256>>>(batch, N);
    k_classify<<<NGR, 128>>>(cls1_w, cls1_b, cls2_w, cls2_b, out);
}

// round 4
// speedup vs baseline: 1.9478x; 1.9478x over previous
#include <cuda_runtime.h>
#include <math.h>

// ---------------- problem constants ----------------
#define MAXN 20000
#define MAXE 320000
#define MAXET (MAXN + MAXE)
#define NGR 32

// ---------------- device scratch (no allocs allowed) ----------------
__device__ float g_h768[MAXN * 768];
__device__ float g_T[(size_t)MAXN * 1024];
__device__ float g_G[(size_t)MAXN * 1024];
__device__ float g_x1[(size_t)MAXN * 1024];
__device__ float g_x2[(size_t)MAXN * 1024];
__device__ float g_x3[MAXN * 256];
__device__ float g_es[MAXN * 4];
__device__ float g_ed[MAXN * 4];
__device__ int   g_deg[MAXN];
__device__ int   g_off[MAXN + 1];
__device__ int   g_cur[MAXN];
__device__ int   g_csr[MAXET];
__device__ float g_psum[NGR * 256];
__device__ float g_pmax[NGR * 256];
__device__ int   g_pcnt[NGR];

// Device-side buffer table: kernel_launch stays pure kernel launches.
#define BUF_H768 0
#define BUF_T    1
#define BUF_G    2
#define BUF_X1   3
#define BUF_X2   4
#define BUF_X3   5
__device__ float* const g_fptr[6] = { g_h768, g_T, g_G, g_x1, g_x2, g_x3 };

// ---------------- helpers ----------------
__device__ __forceinline__ float atomicMaxF(float* addr, float value) {
    if (value >= 0.f)
        return __int_as_float(atomicMax((int*)addr, __float_as_int(value)));
    else
        return __uint_as_float(atomicMin((unsigned int*)addr, __float_as_uint(value)));
}

// ---------------- CSR build ----------------
__global__ void k_zero_deg(int n) {
    int i = blockIdx.x * 256 + threadIdx.x;
    if (i < n) g_deg[i] = 0;
}

__global__ void k_count_deg(const int* __restrict__ ei, int E, int N) {
    int i = blockIdx.x * 256 + threadIdx.x;
    if (i >= E + N) return;
    int dst = (i < E) ? ei[E + i] : (i - E);
    atomicAdd(&g_deg[dst], 1);
}

__global__ void __launch_bounds__(1024) k_scan_deg(int n) {
    const int NT = 1024;
    int tid = threadIdx.x;
    int chunk = (n + NT - 1) / NT;
    int b0 = tid * chunk;
    int lsum = 0;
    for (int i = 0; i < chunk; i++) {
        int j = b0 + i;
        if (j < n) lsum += g_deg[j];
    }
    __shared__ int s[NT];
    s[tid] = lsum;
    __syncthreads();
    for (int o = 1; o < NT; o <<= 1) {
        int t = (tid >= o) ? s[tid - o] : 0;
        __syncthreads();
        s[tid] += t;
        __syncthreads();
    }
    int run = s[tid] - lsum;  // exclusive prefix
    for (int i = 0; i < chunk; i++) {
        int j = b0 + i;
        if (j < n) { g_off[j] = run; g_cur[j] = run; run += g_deg[j]; }
    }
    if (tid == NT - 1) g_off[n] = s[NT - 1];
}

__global__ void k_scatter_edges(const int* __restrict__ ei, int E, int N) {
    int i = blockIdx.x * 256 + threadIdx.x;
    if (i >= E + N) return;
    int src, dst;
    if (i < E) { src = ei[i]; dst = ei[E + i]; }
    else       { src = i - E; dst = i - E; }
    int pos = atomicAdd(&g_cur[dst], 1);
    g_csr[pos] = src;
}

// ---------------- SGEMM: C = act(A @ W + bias) ----------------
// 128x128x16 tiles, 256 threads, 8x8 microtile. N,K multiples of 16/128 as used.
#define TBM 128
#define TBN 128
#define TBK 16
template <int ACT>
__global__ void __launch_bounds__(256) k_sgemm(const float* __restrict__ Aext, int a_id,
                                               const float* __restrict__ W,
                                               const float* __restrict__ bias, int c_id,
                                               int M, int N, int K) {
    const float* __restrict__ A = Aext ? Aext : g_fptr[a_id];
    float* __restrict__ C = g_fptr[c_id];
    __shared__ float As[TBK][TBM + 4];
    __shared__ float Ws[TBK][TBN + 4];
    int tid = threadIdx.x;
    int row0 = blockIdx.y * TBM, col0 = blockIdx.x * TBN;
    int tx = tid & 15, ty = tid >> 4;

    float acc[8][8] = {};

    // A-tile loader: 128 rows x 16 k = 512 float4; thread handles p = 2*tid, 2*tid+1
    // p -> arow = p>>2, acol4 = (p&3)*4 (k offset)
    int p0 = tid * 2;
    // W-tile loader: 16 k x 128 n = 512 float4; p -> wrow = p>>5, wcol = (p&31)*4
    for (int k0 = 0; k0 < K; k0 += TBK) {
#pragma unroll
        for (int i = 0; i < 2; i++) {
            int p = p0 + i;
            int arow = p >> 2, acol4 = (p & 3) * 4;
            float4 av = make_float4(0.f, 0.f, 0.f, 0.f);
            int gr = row0 + arow;
            if (gr < M) av = *(const float4*)(A + (size_t)gr * K + k0 + acol4);
            As[acol4 + 0][arow] = av.x;
            As[acol4 + 1][arow] = av.y;
            As[acol4 + 2][arow] = av.z;
            As[acol4 + 3][arow] = av.w;

            int wrow = p >> 5, wcol = (p & 31) * 4;
            float4 wv = *(const float4*)(W + (size_t)(k0 + wrow) * N + col0 + wcol);
            *(float4*)&Ws[wrow][wcol] = wv;
        }
        __syncthreads();

#pragma unroll
        for (int k = 0; k < TBK; k++) {
            float a[8], b[8];
            *(float4*)&a[0] = *(const float4*)&As[k][ty * 8];
            *(float4*)&a[4] = *(const float4*)&As[k][ty * 8 + 4];
            *(float4*)&b[0] = *(const float4*)&Ws[k][tx * 8];
            *(float4*)&b[4] = *(const float4*)&Ws[k][tx * 8 + 4];
#pragma unroll
            for (int i = 0; i < 8; i++)
#pragma unroll
                for (int j = 0; j < 8; j++) acc[i][j] += a[i] * b[j];
        }
        __syncthreads();
    }

#pragma unroll
    for (int i = 0; i < 8; i++) {
        int r = row0 + ty * 8 + i;
        if (r >= M) continue;
#pragma unroll
        for (int jj = 0; jj < 2; jj++) {
            int c = col0 + tx * 8 + jj * 4;
            float4 v;
            v.x = acc[i][jj * 4 + 0];
            v.y = acc[i][jj * 4 + 1];
            v.z = acc[i][jj * 4 + 2];
            v.w = acc[i][jj * 4 + 3];
            if (bias) {
                v.x += bias[c + 0]; v.y += bias[c + 1];
                v.z += bias[c + 2]; v.w += bias[c + 3];
            }
            if (ACT == 1) {
                v.x = v.x > 0.f ? v.x : (expf(v.x) - 1.0f);
                v.y = v.y > 0.f ? v.y : (expf(v.y) - 1.0f);
                v.z = v.z > 0.f ? v.z : (expf(v.z) - 1.0f);
                v.w = v.w > 0.f ? v.w : (expf(v.w) - 1.0f);
            }
            *(float4*)(C + (size_t)r * N + c) = v;
        }
    }
}

// ---------------- attention dot products ----------------
__global__ void k_att_dots(const float* __restrict__ as_, const float* __restrict__ ad_,
                           int NH, int H, int C) {
    const float* __restrict__ T = g_T;
    int gw = (blockIdx.x * blockDim.x + threadIdx.x) >> 5;
    int lane = threadIdx.x & 31;
    if (gw >= NH) return;
    int n = gw / H, h = gw - n * H;
    const float* row = T + (size_t)n * H * C + (size_t)h * C;
    float a = 0.f, d = 0.f;
    for (int c = lane; c < C; c += 32) {
        float v = row[c];
        a += v * as_[h * C + c];
        d += v * ad_[h * C + c];
    }
    for (int o = 16; o; o >>= 1) {
        a += __shfl_xor_sync(0xffffffffu, a, o);
        d += __shfl_xor_sync(0xffffffffu, d, o);
    }
    if (lane == 0) { g_es[gw] = a; g_ed[gw] = d; }
}

// ---------------- GAT aggregation (per-dst-node softmax + weighted gather) ----------------
template <int H, int CPT>
__global__ void __launch_bounds__(256) k_gat_agg(const float* __restrict__ bias) {
    const int F = 256 * CPT;  // = H*256
    const float* __restrict__ T = g_T;
    const float* __restrict__ es = g_es;
    float* __restrict__ out = g_G;
    int node = blockIdx.x;
    int tid = threadIdx.x;
    int lane = tid & 31, wid = tid >> 5;
    int beg = g_off[node], end = g_off[node + 1];

    float edv[H];
#pragma unroll
    for (int h = 0; h < H; h++) edv[h] = g_ed[node * H + h];

    __shared__ float s_red[8][H];
    __shared__ float s_hmax[H];
    __shared__ float s_hden[H];

    // pass 1: per-head max logit
    float lmax[H];
#pragma unroll
    for (int h = 0; h < H; h++) lmax[h] = -INFINITY;
    for (int e = beg + tid; e < end; e += 256) {
        int s = g_csr[e];
        if (H == 4) {
            float4 e4 = *(const float4*)(es + s * 4);
            float l0 = e4.x + edv[0]; l0 = l0 > 0.f ? l0 : 0.2f * l0; lmax[0] = fmaxf(lmax[0], l0);
            float l1 = e4.y + edv[1]; l1 = l1 > 0.f ? l1 : 0.2f * l1; lmax[1] = fmaxf(lmax[1], l1);
            float l2 = e4.z + edv[2]; l2 = l2 > 0.f ? l2 : 0.2f * l2; lmax[2] = fmaxf(lmax[2], l2);
            float l3 = e4.w + edv[3]; l3 = l3 > 0.f ? l3 : 0.2f * l3; lmax[3] = fmaxf(lmax[3], l3);
        } else {
            float l = es[s * H] + edv[0];
            l = l > 0.f ? l : 0.2f * l;
            lmax[0] = fmaxf(lmax[0], l);
        }
    }
#pragma unroll
    for (int h = 0; h < H; h++)
        for (int o = 16; o; o >>= 1) lmax[h] = fmaxf(lmax[h], __shfl_xor_sync(0xffffffffu, lmax[h], o));
    if (lane == 0) {
#pragma unroll
        for (int h = 0; h < H; h++) s_red[wid][h] = lmax[h];
    }
    __syncthreads();
    if (tid == 0) {
#pragma unroll
        for (int h = 0; h < H; h++) {
            float m = s_red[0][h];
            for (int w = 1; w < 8; w++) m = fmaxf(m, s_red[w][h]);
            s_hmax[h] = m;
        }
    }
    __syncthreads();

    // pass 2: denominator
    float lden[H] = {};
    for (int e = beg + tid; e < end; e += 256) {
        int s = g_csr[e];
        if (H == 4) {
            float4 e4 = *(const float4*)(es + s * 4);
            float l0 = e4.x + edv[0]; l0 = l0 > 0.f ? l0 : 0.2f * l0; lden[0] += expf(l0 - s_hmax[0]);
            float l1 = e4.y + edv[1]; l1 = l1 > 0.f ? l1 : 0.2f * l1; lden[1] += expf(l1 - s_hmax[1]);
            float l2 = e4.z + edv[2]; l2 = l2 > 0.f ? l2 : 0.2f * l2; lden[2] += expf(l2 - s_hmax[2]);
            float l3 = e4.w + edv[3]; l3 = l3 > 0.f ? l3 : 0.2f * l3; lden[3] += expf(l3 - s_hmax[3]);
        } else {
            float l = es[s * H] + edv[0];
            l = l > 0.f ? l : 0.2f * l;
            lden[0] += expf(l - s_hmax[0]);
        }
    }
#pragma unroll
    for (int h = 0; h < H; h++)
        for (int o = 16; o; o >>= 1) lden[h] += __shfl_xor_sync(0xffffffffu, lden[h], o);
    if (lane == 0) {
#pragma unroll
        for (int h = 0; h < H; h++) s_red[wid][h] = lden[h];
    }
    __syncthreads();
    if (tid == 0) {
#pragma unroll
        for (int h = 0; h < H; h++) {
            float m = 0.f;
            for (int w = 0; w < 8; w++) m += s_red[w][h];
            s_hden[h] = m;
        }
    }
    __syncthreads();

    // pass 3: weighted gather
    float acc[CPT] = {};
    __shared__ int s_src[256];
    __shared__ float s_alpha[256 * H];
    for (int cb = beg; cb < end; cb += 256) {
        int cn = min(256, end - cb);
        if (tid < cn) {
            int s = g_csr[cb + tid];
            s_src[tid] = s;
#pragma unroll
            for (int h = 0; h < H; h++) {
                float l = es[s * H + h] + edv[h];
                l = l > 0.f ? l : 0.2f * l;
                s_alpha[tid * H + h] = expf(l - s_hmax[h]) / (s_hden[h] + 1e-16f);
            }
        }
        __syncthreads();
        if (CPT == 4) {
            const int head = tid >> 6;
            for (int j = 0; j < cn; j++) {
                int s = s_src[j];
                float alpha = s_alpha[j * H + head];
                float4 v = *(const float4*)(T + (size_t)s * F + tid * 4);
                acc[0] += alpha * v.x;
                acc[1] += alpha * v.y;
                acc[2] += alpha * v.z;
                acc[3] += alpha * v.w;
            }
        } else {
            for (int j = 0; j < cn; j++) {
                int s = s_src[j];
                float alpha = s_alpha[j * H];
                acc[0] += alpha * T[(size_t)s * F + tid];
            }
        }
        __syncthreads();
    }
#pragma unroll
    for (int q = 0; q < CPT; q++) {
        int c = tid * CPT + q;
        out[(size_t)node * F + c] = acc[q] + bias[c];
    }
}

// ---------------- LayerNorm + ELU (+ optional residual added AFTER elu) ----------------
// in = g_G always; res/out selected by id (res_id < 0 -> none). F multiple of 4.
__global__ void __launch_bounds__(256) k_ln_elu(const float* __restrict__ g,
                                                const float* __restrict__ b,
                                                int res_id, int out_id, int F) {
    const float* __restrict__ in = g_G;
    const float* __restrict__ res = (res_id >= 0) ? g_fptr[res_id] : nullptr;
    float* __restrict__ out = g_fptr[out_id];
    int node = blockIdx.x, tid = threadIdx.x;
    const float* row = in + (size_t)node * F;
    int nv = F >> 2;
    float s = 0.f, s2 = 0.f;
    for (int q = tid; q < nv; q += 256) {
        float4 v = *(const float4*)(row + q * 4);
        s += v.x + v.y + v.z + v.w;
        s2 += v.x * v.x + v.y * v.y + v.z * v.z + v.w * v.w;
    }
    __shared__ float sh[8], sh2[8];
    for (int o = 16; o; o >>= 1) {
        s += __shfl_xor_sync(0xffffffffu, s, o);
        s2 += __shfl_xor_sync(0xffffffffu, s2, o);
    }
    if ((tid & 31) == 0) { sh[tid >> 5] = s; sh2[tid >> 5] = s2; }
    __syncthreads();
    __shared__ float smean, sinv;
    if (tid == 0) {
        float ts = 0.f, t2 = 0.f;
        for (int w = 0; w < 8; w++) { ts += sh[w]; t2 += sh2[w]; }
        float mean = ts / F;
        float var = t2 / F - mean * mean;
        if (var < 0.f) var = 0.f;
        smean = mean;
        sinv = rsqrtf(var + 1e-5f);
    }
    __syncthreads();
    float mean = smean, inv = sinv;
    for (int q = tid; q < nv; q += 256) {
        int c = q * 4;
        float4 v = *(const float4*)(row + c);
        float4 gg = *(const float4*)(g + c);
        float4 bb = *(const float4*)(b + c);
        v.x = (v.x - mean) * inv * gg.x + bb.x;
        v.y = (v.y - mean) * inv * gg.y + bb.y;
        v.z = (v.z - mean) * inv * gg.z + bb.z;
        v.w = (v.w - mean) * inv * gg.w + bb.w;
        v.x = v.x > 0.f ? v.x : (expf(v.x) - 1.0f);
        v.y = v.y > 0.f ? v.y : (expf(v.y) - 1.0f);
        v.z = v.z > 0.f ? v.z : (expf(v.z) - 1.0f);
        v.w = v.w > 0.f ? v.w : (expf(v.w) - 1.0f);
        if (res) {
            float4 rr = *(const float4*)(res + (size_t)node * F + c);
            v.x += rr.x; v.y += rr.y; v.z += rr.z; v.w += rr.w;
        }
        *(float4*)(out + (size_t)node * F + c) = v;
    }
}

// ---------------- pooling ----------------
__global__ void k_pool_init() {
    int i = blockIdx.x * 256 + threadIdx.x;
    if (i < NGR * 256) { g_psum[i] = 0.f; g_pmax[i] = -INFINITY; }
    if (i < NGR) g_pcnt[i] = 0;
}

__global__ void k_pool_scatter(const int* __restrict__ batch, int N) {
    int i = blockIdx.x * 256 + threadIdx.x;
    if (i >= N * 256) return;
    int n = i >> 8, c = i & 255;
    int gph = batch[n];
    float v = g_x3[(size_t)n * 256 + c];
    atomicAdd(&g_psum[gph * 256 + c], v);
    atomicMaxF(&g_pmax[gph * 256 + c], v);
    if (c == 0) atomicAdd(&g_pcnt[gph], 1);
}

// ---------------- classifier head ----------------
__global__ void __launch_bounds__(128) k_classify(const float* __restrict__ w1, const float* __restrict__ b1,
                                                  const float* __restrict__ w2, const float* __restrict__ b2,
                                                  float* __restrict__ out) {
    int gph = blockIdx.x, tid = threadIdx.x;
    __shared__ float p[768];
    float cnt = (float)max(g_pcnt[gph], 1);
    for (int j = tid; j < 256; j += 128) {
        float sm = g_psum[gph * 256 + j];
        p[j] = sm / cnt;
        p[256 + j] = g_pmax[gph * 256 + j];
        p[512 + j] = sm;
    }
    __syncthreads();
    float h = b1[tid];
    for (int j = 0; j < 768; j++) h += p[j] * w1[j * 128 + tid];
    h = h > 0.f ? h : 0.f;
    float part = h * w2[tid];
    for (int o = 16; o; o >>= 1) part += __shfl_xor_sync(0xffffffffu, part, o);
    __shared__ float sr[4];
    if ((tid & 31) == 0) sr[tid >> 5] = part;
    __syncthreads();
    if (tid == 0) out[gph] = sr[0] + sr[1] + sr[2] + sr[3] + b2[0];
}

// ---------------- launch (pure kernel launches; graph-capture safe) ----------------
extern "C" void kernel_launch(void* const* d_in, const int* in_sizes, int n_in,
                              void* d_out, int out_size) {
    const float* x = (const float*)d_in[0];
    const int* ei = (const int*)d_in[1];
    const int* batch = (const int*)d_in[2];
    const float* proj_w = (const float*)d_in[3];
    const float* proj_b = (const float*)d_in[4];
    const float* gat1_w = (const float*)d_in[5];
    const float* att1_src = (const float*)d_in[6];
    const float* att1_dst = (const float*)d_in[7];
    const float* gat1_b = (const float*)d_in[8];
    const float* ln1_g = (const float*)d_in[9];
    const float* ln1_b = (const float*)d_in[10];
    const float* gat2_w = (const float*)d_in[11];
    const float* att2_src = (const float*)d_in[12];
    const float* att2_dst = (const float*)d_in[13];
    const float* gat2_b = (const float*)d_in[14];
    const float* ln2_g = (const float*)d_in[15];
    const float* ln2_b = (const float*)d_in[16];
    const float* gat3_w = (const float*)d_in[17];
    const float* att3_src = (const float*)d_in[18];
    const float* att3_dst = (const float*)d_in[19];
    const float* gat3_b = (const float*)d_in[20];
    const float* ln3_g = (const float*)d_in[21];
    const float* ln3_b = (const float*)d_in[22];
    const float* cls1_w = (const float*)d_in[23];
    const float* cls1_b = (const float*)d_in[24];
    const float* cls2_w = (const float*)d_in[25];
    const float* cls2_b = (const float*)d_in[26];
    float* out = (float*)d_out;

    int N = in_sizes[0] / 768;
    int E = in_sizes[1] / 2;
    int ET = E + N;

    // ---- CSR build (dst-grouped incoming edges incl. self-loops) ----
    k_zero_deg<<<(N + 255) / 256, 256>>>(N);
    k_count_deg<<<(ET + 255) / 256, 256>>>(ei, E, N);
    k_scan_deg<<<1, 1024>>>(N);
    k_scatter_edges<<<(ET + 255) / 256, 256>>>(ei, E, N);

    dim3 thr(256);
    int mgrid = (N + TBM - 1) / TBM;

    // ---- h = elu(x @ proj_w + proj_b) ----
    k_sgemm<1><<<dim3(768 / TBN, mgrid), thr>>>(x, 0, proj_w, proj_b, BUF_H768, N, 768, 768);

    // ---- GAT layer 1: 768 -> 4x256 concat ----
    k_sgemm<0><<<dim3(1024 / TBN, mgrid), thr>>>(nullptr, BUF_H768, gat1_w, nullptr, BUF_T, N, 1024, 768);
    k_att_dots<<<(N * 4 * 32 + 255) / 256, 256>>>(att1_src, att1_dst, N * 4, 4, 256);
    k_gat_agg<4, 4><<<N, 256>>>(gat1_b);
    k_ln_elu<<<N, 256>>>(ln1_g, ln1_b, -1, BUF_X1, 1024);

    // ---- GAT layer 2: 1024 -> 4x256 concat, residual ----
    k_sgemm<0><<<dim3(1024 / TBN, mgrid), thr>>>(nullptr, BUF_X1, gat2_w, nullptr, BUF_T, N, 1024, 1024);
    k_att_dots<<<(N * 4 * 32 + 255) / 256, 256>>>(att2_src, att2_dst, N * 4, 4, 256);
    k_gat_agg<4, 4><<<N, 256>>>(gat2_b);
    k_ln_elu<<<N, 256>>>(ln2_g, ln2_b, BUF_X1, BUF_X2, 1024);

    // ---- GAT layer 3: 1024 -> 1x256 (mean over 1 head = identity) ----
    k_sgemm<0><<<dim3(256 / TBN, mgrid), thr>>>(nullptr, BUF_X2, gat3_w, nullptr, BUF_T, N, 256, 1024);
    k_att_dots<<<(N * 1 * 32 + 255) / 256, 256>>>(att3_src, att3_dst, N * 1, 1, 256);
    k_gat_agg<1, 1><<<N, 256>>>(gat3_b);
    k_ln_elu<<<N, 256>>>(ln3_g, ln3_b, -1, BUF_X3, 256);

    // ---- pooling + classifier ----
    k_pool_init<<<(NGR * 256 + 255) / 256, 256>>>();
    k_pool_scatter<<<(N * 256 + 255) / 256, 256>>>(batch, N);
    k_classify<<<NGR, 128>>>(cls1_w, cls1_b, cls2_w, cls2_b, out);
}